// round 17
// baseline (speedup 1.0000x reference)
#include <cuda_runtime.h>
#include <cuda_bf16.h>
#include <math.h>
#include <stdint.h>

#define BB   8
#define NCELL 1024
#define SLEN 1025
#define D    256
#define NH   8
#define HD   32
#define DFF  1024
#define NL   4
#define MTOK (BB*SLEN)   // 8200

// cp.async helper: 16B global->shared, zero-fill when sz==0
#define CPA16(dst, src, sz) \
    asm volatile("cp.async.cg.shared.global [%0], [%1], 16, %2;" \
        :: "r"((uint32_t)__cvta_generic_to_shared(dst)), "l"(src), "r"(sz))

// bf16 tensor-core mma: C(f32) += A(bf16) * B(bf16), m16n8k16 row.col
#define MMA_BF16(c, a, b) \
    asm volatile("mma.sync.aligned.m16n8k16.row.col.f32.bf16.bf16.f32 " \
        "{%0,%1,%2,%3}, {%4,%5,%6,%7}, {%8,%9}, {%0,%1,%2,%3};" \
        : "+f"((c)[0]), "+f"((c)[1]), "+f"((c)[2]), "+f"((c)[3]) \
        : "r"((a)[0]), "r"((a)[1]), "r"((a)[2]), "r"((a)[3]), \
          "r"((b)[0]), "r"((b)[1]))

#define LDSM4(d0,d1,d2,d3,a) \
    asm volatile("ldmatrix.sync.aligned.m8n8.x4.shared.b16 {%0,%1,%2,%3}, [%4];" \
        : "=r"(d0),"=r"(d1),"=r"(d2),"=r"(d3) : "r"(a))
#define LDSM4T(d0,d1,d2,d3,a) \
    asm volatile("ldmatrix.sync.aligned.m8n8.x4.trans.shared.b16 {%0,%1,%2,%3}, [%4];" \
        : "=r"(d0),"=r"(d1),"=r"(d2),"=r"(d3) : "r"(a))

#define CVTPK(d, hi, lo) \
    asm("cvt.rn.bf16x2.f32 %0, %1, %2;" : "=r"(d) : "f"(hi), "f"(lo))

__device__ __forceinline__ uint32_t sptr(const void* p) {
    return (uint32_t)__cvta_generic_to_shared(p);
}

// pack (p0,p1) -> bf16x2 hi word + bf16x2 residual word
__device__ __forceinline__ void psplit(float p0, float p1, uint32_t& hi, uint32_t& lo)
{
    CVTPK(hi, p1, p0);
    float f0 = __uint_as_float(hi << 16);
    float f1 = __uint_as_float(hi & 0xffff0000u);
    CVTPK(lo, p1 - f1, p0 - f0);
}

// ---------------- scratch (static device globals; no allocs) ----------------
__device__ float g_x[MTOK*D];
__device__ float g_t[MTOK*D];

// bf16 hi/lo split activations
__device__ __nv_bfloat16 g_xh[MTOK*D],  g_xl[MTOK*D];
__device__ __nv_bfloat16 g_ah[MTOK*D],  g_al[MTOK*D];
__device__ __nv_bfloat16 g_hh[(size_t)MTOK*DFF], g_hl[(size_t)MTOK*DFF];
__device__ __nv_bfloat16 g_qh[MTOK*D],  g_ql[MTOK*D];
__device__ __nv_bfloat16 g_kh[MTOK*D],  g_kl[MTOK*D];
__device__ __nv_bfloat16 g_vh[MTOK*D],  g_vl[MTOK*D];

// bf16 hi/lo split transposed weights [N][K]
#define WOFF_WO  (12*D*D)
#define WOFF_F1  (16*D*D)
#define WOFF_F2  (WOFF_F1 + 4*D*DFF)
#define WT_TOTAL (WOFF_F2 + 4*D*DFF)
__device__ __nv_bfloat16 g_wth[WT_TOTAL], g_wtl[WT_TOTAL];

__device__ __forceinline__ __nv_bfloat162 bsplit2(float a, float b, __nv_bfloat162* lo)
{
    __nv_bfloat16 ha = __float2bfloat16_rn(a);
    __nv_bfloat16 hb = __float2bfloat16_rn(b);
    lo->x = __float2bfloat16_rn(a - __bfloat162float(ha));
    lo->y = __float2bfloat16_rn(b - __bfloat162float(hb));
    __nv_bfloat162 hi; hi.x = ha; hi.y = hb;
    return hi;
}

// ---------------- embedding: emb + cell-type MLP + positional + cls ----------
__global__ void embed_kernel(const float* __restrict__ cf,
                             const int* __restrict__ xc,
                             const int* __restrict__ yc,
                             const float* __restrict__ Wemb,
                             const float* __restrict__ bemb,
                             const float* __restrict__ Wct1,
                             const float* __restrict__ bct1,
                             const float* __restrict__ Wct2,
                             const float* __restrict__ bct2,
                             const float* __restrict__ cls)
{
    int blk = blockIdx.x;          // 0..8199
    int b = blk / SLEN;
    int s = blk % SLEN;
    int d = threadIdx.x;           // 0..255
    float* out = g_x + (size_t)blk * D;

    float val;
    if (s == 0) {
        val = cls[d];
    } else {
        int n = s - 1;
        __shared__ float cfs[64];
        __shared__ float hs[128];
        const float* cfp = cf + ((size_t)b*NCELL + n)*64;
        if (d < 64) cfs[d] = cfp[d];
        __syncthreads();

        if (d < 128) {
            float acc = bct1[d];
            #pragma unroll
            for (int k = 0; k < 64; k++) acc = fmaf(cfs[k], Wct1[k*128 + d], acc);
            hs[d] = fmaxf(acc, 0.f);
        }
        __syncthreads();

        float e = bemb[d];
        #pragma unroll
        for (int k = 0; k < 64; k++) e = fmaf(cfs[k], Wemb[k*256 + d], e);
        float c2 = bct2[d];
        #pragma unroll
        for (int j = 0; j < 128; j++) c2 = fmaf(hs[j], Wct2[j*256 + d], c2);

        int dd    = (d < 128) ? d : d - 128;
        int coord = (d < 128) ? xc[b*NCELL + n] : yc[b*NCELL + n];
        coord = min(max(coord, 0), 999);
        int m = dd >> 1;
        const float c1 = -0.07195578739046225f;  // float(-ln(10000)/128)
        float dv  = expf((float)(2*m) * c1);
        float ang = (float)coord * dv;
        float p   = (dd & 1) ? cosf(ang) : sinf(ang);
        val = e + c2 + p;
    }

    out[d] = val;
    __nv_bfloat16 hh = __float2bfloat16_rn(val);
    g_xh[(size_t)blk*D + d] = hh;
    g_xl[(size_t)blk*D + d] = __float2bfloat16_rn(val - __bfloat162float(hh));
}

// ----- weight convert: W[K][N] f32 -> Wt[N][K] bf16 hi/lo, coalesced ---------
// 32x32 smem transpose tile, grid (K/32, N/32, NL), 256 threads
__global__ void wconv_kernel(const float* __restrict__ src,
                             __nv_bfloat16* __restrict__ dh,
                             __nv_bfloat16* __restrict__ dl,
                             int K, int N, int srcStride, int dstStride)
{
    __shared__ float tile[32][33];
    int l  = blockIdx.z;
    int k0 = blockIdx.x * 32, n0 = blockIdx.y * 32;
    int tx = threadIdx.x & 31, ty = threadIdx.x >> 5;   // ty 0..7
    const float* s = src + (size_t)l * srcStride;
    #pragma unroll
    for (int i = 0; i < 4; i++) {
        int r = ty + i*8;
        tile[r][tx] = s[(size_t)(k0 + r)*N + n0 + tx];
    }
    __syncthreads();
    #pragma unroll
    for (int i = 0; i < 4; i++) {
        int n = ty + i*8;
        float v = tile[tx][n];
        __nv_bfloat16 h = __float2bfloat16_rn(v);
        size_t o = (size_t)l*dstStride + (size_t)(n0 + n)*K + k0 + tx;
        dh[o] = h;
        dl[o] = __float2bfloat16_rn(v - __bfloat162float(h));
    }
}

// ---- bf16x3 tensor-core GEMM: C = (A@W + bias)*oscale; BM=64 BN=128 BK=16 ---
// 256 threads / 8 warps (2m x 4n), warp tile 32x32. Double-buffered smem.
__device__ __forceinline__
void mma_body(const __nv_bfloat16* __restrict__ Agh,
              const __nv_bfloat16* __restrict__ Agl,
              const __nv_bfloat16* __restrict__ Bgh,
              const __nv_bfloat16* __restrict__ Bgl,
              const float* __restrict__ bias,
              float* __restrict__ Cf,
              __nv_bfloat16* __restrict__ Ch,
              __nv_bfloat16* __restrict__ Cl,
              int M, int N, int K, int relu, float oscale, int bx, int by)
{
    __shared__ __align__(16) __nv_bfloat16 Ahs[2][64][24],  Als[2][64][24];
    __shared__ __align__(16) __nv_bfloat16 Bhs[2][128][24], Bls[2][128][24];

    int tid  = threadIdx.x;        // 0..255
    int lane = tid & 31;
    int wid  = tid >> 5;           // 0..7
    int m0 = bx * 64, n0 = by * 128;
    int g = lane >> 2, t = lane & 3;
    int mw = (wid & 1) * 32;
    int nw = (wid >> 1) * 32;      // 0,32,64,96

    // A load: each thread covers one 16B chunk of Ah OR Al
    int aarr = tid >> 7;           // 0: hi, 1: lo
    int aidx = tid & 127;
    int arow = aidx >> 1;          // 0..63
    int acol = (aidx & 1) * 8;
    int gr = m0 + arow;
    int szA = (gr < M) ? 16 : 0;
    int cr  = min(gr, M-1);
    const __nv_bfloat16* pA = (aarr ? Agl : Agh) + (size_t)cr*K + acol;

    // B load: each thread one 16B chunk of Bh and one of Bl
    int brow = tid >> 1;           // 0..127
    int bcol = (tid & 1) * 8;
    const __nv_bfloat16* pBh = Bgh + (size_t)(n0 + brow)*K + bcol;
    const __nv_bfloat16* pBl = Bgl + (size_t)(n0 + brow)*K + bcol;

    float acc[2][4][4];
    #pragma unroll
    for (int mt = 0; mt < 2; mt++)
        #pragma unroll
        for (int nt = 0; nt < 4; nt++)
            #pragma unroll
            for (int i = 0; i < 4; i++) acc[mt][nt][i] = 0.f;

#define ISSUE_TILE(buf, kt) do { \
    int _k0 = (kt)*16; \
    __nv_bfloat16* _ad = aarr ? &Als[buf][arow][acol] : &Ahs[buf][arow][acol]; \
    CPA16(_ad, pA + _k0, szA); \
    CPA16(&Bhs[buf][brow][bcol], pBh + _k0, 16); \
    CPA16(&Bls[buf][brow][bcol], pBl + _k0, 16); \
    asm volatile("cp.async.commit_group;"); \
} while (0)

    ISSUE_TILE(0, 0);

    int KT = K >> 4;
    for (int kt = 0; kt < KT; kt++) {
        int cur = kt & 1;
        if (kt + 1 < KT) {
            ISSUE_TILE(cur ^ 1, kt + 1);
            asm volatile("cp.async.wait_group 1;");
        } else {
            asm volatile("cp.async.wait_group 0;");
        }
        __syncthreads();

        // A fragments (m16k16): row = base+(lane&15), col = (lane>>4)*8
        uint32_t ahf[2][4], alf[2][4];
        #pragma unroll
        for (int mt = 0; mt < 2; mt++) {
            int r  = mw + mt*16 + (lane & 15);
            int cb = (lane >> 4) * 8;
            LDSM4(ahf[mt][0], ahf[mt][1], ahf[mt][2], ahf[mt][3],
                  sptr(&Ahs[cur][r][cb]));
            LDSM4(alf[mt][0], alf[mt][1], alf[mt][2], alf[mt][3],
                  sptr(&Als[cur][r][cb]));
        }

        // B fragments: one x4 covers TWO n-tiles (n8 x k16 each)
        #pragma unroll
        for (int np = 0; np < 2; np++) {
            uint32_t bh4[4], bl4[4];
            int j  = lane >> 3;
            int rr = nw + np*16 + ((j >> 1) << 3) + (lane & 7);
            int cc = (j & 1) * 8;
            LDSM4(bh4[0], bh4[1], bh4[2], bh4[3], sptr(&Bhs[cur][rr][cc]));
            LDSM4(bl4[0], bl4[1], bl4[2], bl4[3], sptr(&Bls[cur][rr][cc]));
            #pragma unroll
            for (int hf = 0; hf < 2; hf++) {
                int nt = np*2 + hf;
                #pragma unroll
                for (int mt = 0; mt < 2; mt++) {
                    MMA_BF16(acc[mt][nt], ahf[mt], bh4 + 2*hf);
                    MMA_BF16(acc[mt][nt], ahf[mt], bl4 + 2*hf);
                    MMA_BF16(acc[mt][nt], alf[mt], bh4 + 2*hf);
                }
            }
        }
        __syncthreads();
    }
#undef ISSUE_TILE

    // epilogue
    #pragma unroll
    for (int mt = 0; mt < 2; mt++) {
        #pragma unroll
        for (int nt = 0; nt < 4; nt++) {
            int col = n0 + nw + nt*8 + 2*t;
            float b0v = bias[col], b1v = bias[col+1];
            int r0 = m0 + mw + mt*16 + g;
            int r1 = r0 + 8;
            float v00 = (acc[mt][nt][0] + b0v) * oscale;
            float v01 = (acc[mt][nt][1] + b1v) * oscale;
            float v10 = (acc[mt][nt][2] + b0v) * oscale;
            float v11 = (acc[mt][nt][3] + b1v) * oscale;
            if (relu) {
                v00 = fmaxf(v00, 0.f); v01 = fmaxf(v01, 0.f);
                v10 = fmaxf(v10, 0.f); v11 = fmaxf(v11, 0.f);
            }
            if (Cf) {
                if (r0 < M) { float2 o = {v00, v01}; *(float2*)(Cf + (size_t)r0*N + col) = o; }
                if (r1 < M) { float2 o = {v10, v11}; *(float2*)(Cf + (size_t)r1*N + col) = o; }
            } else {
                if (r0 < M) {
                    __nv_bfloat162 lo; __nv_bfloat162 hi = bsplit2(v00, v01, &lo);
                    *(__nv_bfloat162*)(Ch + (size_t)r0*N + col) = hi;
                    *(__nv_bfloat162*)(Cl + (size_t)r0*N + col) = lo;
                }
                if (r1 < M) {
                    __nv_bfloat162 lo; __nv_bfloat162 hi = bsplit2(v10, v11, &lo);
                    *(__nv_bfloat162*)(Ch + (size_t)r1*N + col) = hi;
                    *(__nv_bfloat162*)(Cl + (size_t)r1*N + col) = lo;
                }
            }
        }
    }
}

__global__ __launch_bounds__(256, 2)
void mma_gemm(const __nv_bfloat16* __restrict__ Agh,
              const __nv_bfloat16* __restrict__ Agl,
              const __nv_bfloat16* __restrict__ Bgh,
              const __nv_bfloat16* __restrict__ Bgl,
              const float* __restrict__ bias,
              float* __restrict__ Cf,
              __nv_bfloat16* __restrict__ Ch,
              __nv_bfloat16* __restrict__ Cl,
              int M, int N, int K, int relu)
{
    mma_body(Agh, Agl, Bgh, Bgl, bias, Cf, Ch, Cl, M, N, K, relu, 1.f,
             blockIdx.x, blockIdx.y);
}

// fused QKV: writes bf16-split Q (pre-scaled by 1/sqrt(hd)), K, V
__global__ __launch_bounds__(256, 2)
void qkv_mma(const __nv_bfloat16* __restrict__ xh,
             const __nv_bfloat16* __restrict__ xl,
             const __nv_bfloat16* __restrict__ wth,
             const __nv_bfloat16* __restrict__ wtl,
             const float* __restrict__ bq,
             const float* __restrict__ bk,
             const float* __restrict__ bv,
             __nv_bfloat16* __restrict__ Qh, __nv_bfloat16* __restrict__ Ql,
             __nv_bfloat16* __restrict__ Kh, __nv_bfloat16* __restrict__ Kl,
             __nv_bfloat16* __restrict__ Vh, __nv_bfloat16* __restrict__ Vl)
{
    int z = blockIdx.z;
    const __nv_bfloat16* Wh = wth + (size_t)z*D*D;
    const __nv_bfloat16* Wl = wtl + (size_t)z*D*D;
    const float* bias = (z == 0) ? bq : (z == 1) ? bk : bv;
    __nv_bfloat16* Ch = (z == 0) ? Qh : (z == 1) ? Kh : Vh;
    __nv_bfloat16* Cl = (z == 0) ? Ql : (z == 1) ? Kl : Vl;
    float sc = (z == 0) ? 0.17677669529663687f : 1.f;
    mma_body(xh, xl, Wh, Wl, bias, nullptr, Ch, Cl, MTOK, D, D, 0, sc,
             blockIdx.x, blockIdx.y);
}

// -------- tensor-core flash attention (bf16x3), q-tile 128, 8 warps ----------
// K/V double-buffered in smem; Q fragments loaded directly from global.
__global__ __launch_bounds__(256, 2)
void attn_mma_kernel()
{
    __shared__ __align__(16) __nv_bfloat16 pool[2][4][64][40];  // 40960 B

    int qt = blockIdx.x;           // 0..8 (128-row q tiles)
    int h  = blockIdx.y;
    int b  = blockIdx.z;
    int tid = threadIdx.x, lane = tid & 31, w = tid >> 5;  // w 0..7
    int g = lane >> 2, t = lane & 3;
    int mw = w * 16;               // 0..112

    size_t hoff = ((size_t)b * SLEN) * D + h * HD;
    const __nv_bfloat16* qhg = g_qh + hoff;
    const __nv_bfloat16* qlg = g_ql + hoff;
    const __nv_bfloat16* khg = g_kh + hoff;
    const __nv_bfloat16* klg = g_kl + hoff;
    const __nv_bfloat16* vhg = g_vh + hoff;
    const __nv_bfloat16* vlg = g_vl + hoff;

    // K/V tile load mapping: 256 threads, 1 16B chunk per array per thread
    int lr = tid >> 2;             // 0..63
    int lc = (tid & 3) * 8;        // 0,8,16,24 (bf16 offset)

#define KSH(buf) (pool[buf][0])
#define KSL(buf) (pool[buf][1])
#define VSH(buf) (pool[buf][2])
#define VSL(buf) (pool[buf][3])

#define AT_ISSUE(buf, kt) do { \
    int _ck = min((kt)*64 + lr, SLEN-1); \
    CPA16(&KSH(buf)[lr][lc], khg + (size_t)_ck*D + lc, 16); \
    CPA16(&KSL(buf)[lr][lc], klg + (size_t)_ck*D + lc, 16); \
    CPA16(&VSH(buf)[lr][lc], vhg + (size_t)_ck*D + lc, 16); \
    CPA16(&VSL(buf)[lr][lc], vlg + (size_t)_ck*D + lc, 16); \
    asm volatile("cp.async.commit_group;"); \
} while (0)

    AT_ISSUE(0, 0);

    // Q fragments (A m16k16) loaded directly from global
    uint32_t qfh[2][4], qfl[2][4];
    {
        int r0 = min(qt*128 + mw + g,     SLEN-1);
        int r1 = min(qt*128 + mw + g + 8, SLEN-1);
        const __nv_bfloat16* h0 = qhg + (size_t)r0*D;
        const __nv_bfloat16* h1 = qhg + (size_t)r1*D;
        const __nv_bfloat16* l0 = qlg + (size_t)r0*D;
        const __nv_bfloat16* l1 = qlg + (size_t)r1*D;
        #pragma unroll
        for (int ks = 0; ks < 2; ks++) {
            int c0 = ks*16 + 2*t;
            qfh[ks][0] = *(const uint32_t*)(h0 + c0);
            qfh[ks][1] = *(const uint32_t*)(h1 + c0);
            qfh[ks][2] = *(const uint32_t*)(h0 + c0 + 8);
            qfh[ks][3] = *(const uint32_t*)(h1 + c0 + 8);
            qfl[ks][0] = *(const uint32_t*)(l0 + c0);
            qfl[ks][1] = *(const uint32_t*)(l1 + c0);
            qfl[ks][2] = *(const uint32_t*)(l0 + c0 + 8);
            qfl[ks][3] = *(const uint32_t*)(l1 + c0 + 8);
        }
    }

    float m0 = -INFINITY, m1 = -INFINITY, l0 = 0.f, l1 = 0.f;
    float o[4][4];
    #pragma unroll
    for (int nd = 0; nd < 4; nd++)
        #pragma unroll
        for (int i = 0; i < 4; i++) o[nd][i] = 0.f;

    for (int kt = 0; kt < 17; kt++) {
        int cur = kt & 1;
        int k0 = kt * 64;
        if (kt + 1 < 17) {
            AT_ISSUE(cur ^ 1, kt + 1);
            asm volatile("cp.async.wait_group 1;");
        } else {
            asm volatile("cp.async.wait_group 0;");
        }
        __syncthreads();

        // ---- S = Q K^T (3-term bf16x3) ----
        float s[8][4];
        #pragma unroll
        for (int j = 0; j < 8; j++)
            #pragma unroll
            for (int i = 0; i < 4; i++) s[j][i] = 0.f;

        #pragma unroll
        for (int j = 0; j < 8; j++) {
            uint32_t bh[4], bl[4];
            int rr = j*8 + (lane & 7);
            int cc = ((lane >> 3) & 3) * 8;
            LDSM4(bh[0], bh[1], bh[2], bh[3], sptr(&KSH(cur)[rr][cc]));
            LDSM4(bl[0], bl[1], bl[2], bl[3], sptr(&KSL(cur)[rr][cc]));
            MMA_BF16(s[j], qfh[0], bh);
            MMA_BF16(s[j], qfh[1], bh + 2);
            MMA_BF16(s[j], qfh[0], bl);
            MMA_BF16(s[j], qfh[1], bl + 2);
            MMA_BF16(s[j], qfl[0], bh);
            MMA_BF16(s[j], qfl[1], bh + 2);
        }

        // mask invalid tokens (only last tile)
        if (k0 + 64 > SLEN) {
            #pragma unroll
            for (int j = 0; j < 8; j++) {
                int tok = k0 + j*8 + 2*t;
                if (tok     >= SLEN) { s[j][0] = -1e30f; s[j][2] = -1e30f; }
                if (tok + 1 >= SLEN) { s[j][1] = -1e30f; s[j][3] = -1e30f; }
            }
        }

        // ---- online softmax ----
        float t0v = -INFINITY, t1v = -INFINITY;
        #pragma unroll
        for (int j = 0; j < 8; j++) {
            t0v = fmaxf(t0v, fmaxf(s[j][0], s[j][1]));
            t1v = fmaxf(t1v, fmaxf(s[j][2], s[j][3]));
        }
        t0v = fmaxf(t0v, __shfl_xor_sync(0xffffffffu, t0v, 1));
        t0v = fmaxf(t0v, __shfl_xor_sync(0xffffffffu, t0v, 2));
        t1v = fmaxf(t1v, __shfl_xor_sync(0xffffffffu, t1v, 1));
        t1v = fmaxf(t1v, __shfl_xor_sync(0xffffffffu, t1v, 2));

        float mn0 = fmaxf(m0, t0v), mn1 = fmaxf(m1, t1v);
        float c0 = __expf(m0 - mn0), c1 = __expf(m1 - mn1);
        l0 *= c0; l1 *= c1;
        #pragma unroll
        for (int nd = 0; nd < 4; nd++) {
            o[nd][0] *= c0; o[nd][1] *= c0;
            o[nd][2] *= c1; o[nd][3] *= c1;
        }

        float ls0 = 0.f, ls1 = 0.f;
        #pragma unroll
        for (int j = 0; j < 8; j++) {
            s[j][0] = __expf(s[j][0] - mn0); ls0 += s[j][0];
            s[j][1] = __expf(s[j][1] - mn0); ls0 += s[j][1];
            s[j][2] = __expf(s[j][2] - mn1); ls1 += s[j][2];
            s[j][3] = __expf(s[j][3] - mn1); ls1 += s[j][3];
        }
        l0 += ls0; l1 += ls1;
        m0 = mn0; m1 = mn1;

        // ---- P -> A fragments (hi/lo split, in registers) ----
        uint32_t ph[4][4], pl[4][4];
        #pragma unroll
        for (int c = 0; c < 4; c++) {
            psplit(s[2*c][0],   s[2*c][1],   ph[c][0], pl[c][0]);
            psplit(s[2*c][2],   s[2*c][3],   ph[c][1], pl[c][1]);
            psplit(s[2*c+1][0], s[2*c+1][1], ph[c][2], pl[c][2]);
            psplit(s[2*c+1][2], s[2*c+1][3], ph[c][3], pl[c][3]);
        }

        // ---- O += P V (3-term) ----
        #pragma unroll
        for (int nd = 0; nd < 4; nd++) {
            uint32_t bvh[4][2], bvl[4][2];
            #pragma unroll
            for (int cc = 0; cc < 2; cc++) {
                uint32_t va = sptr(&VSH(cur)[cc*32 + lane][nd*8]);
                uint32_t la = sptr(&VSL(cur)[cc*32 + lane][nd*8]);
                LDSM4T(bvh[2*cc][0], bvh[2*cc][1], bvh[2*cc+1][0], bvh[2*cc+1][1], va);
                LDSM4T(bvl[2*cc][0], bvl[2*cc][1], bvl[2*cc+1][0], bvl[2*cc+1][1], la);
            }
            #pragma unroll
            for (int c = 0; c < 4; c++) {
                MMA_BF16(o[nd], ph[c], bvh[c]);
                MMA_BF16(o[nd], ph[c], bvl[c]);
                MMA_BF16(o[nd], pl[c], bvh[c]);
            }
        }
        __syncthreads();   // reads of 'cur' done before next issue into it
    }
#undef AT_ISSUE
#undef KSH
#undef KSL
#undef VSH
#undef VSL

    // final: reduce l over quad, normalize, write bf16-split output
    l0 += __shfl_xor_sync(0xffffffffu, l0, 1);
    l0 += __shfl_xor_sync(0xffffffffu, l0, 2);
    l1 += __shfl_xor_sync(0xffffffffu, l1, 1);
    l1 += __shfl_xor_sync(0xffffffffu, l1, 2);
    float i0 = 1.f / l0, i1 = 1.f / l1;

    int q0 = qt*128 + mw + g;
    int q1 = q0 + 8;
    int colb = h*HD + 2*t;
    #pragma unroll
    for (int nd = 0; nd < 4; nd++) {
        if (q0 < SLEN) {
            __nv_bfloat162 lo;
            __nv_bfloat162 hi = bsplit2(o[nd][0]*i0, o[nd][1]*i0, &lo);
            size_t off = ((size_t)b*SLEN + q0)*D + colb + nd*8;
            *(__nv_bfloat162*)(g_ah + off) = hi;
            *(__nv_bfloat162*)(g_al + off) = lo;
        }
        if (q1 < SLEN) {
            __nv_bfloat162 lo;
            __nv_bfloat162 hi = bsplit2(o[nd][2]*i1, o[nd][3]*i1, &lo);
            size_t off = ((size_t)b*SLEN + q1)*D + colb + nd*8;
            *(__nv_bfloat162*)(g_ah + off) = hi;
            *(__nv_bfloat162*)(g_al + off) = lo;
        }
    }
}

// ---------- fused residual + LayerNorm, warp-per-row; f32 + bf16-split out ---
__global__ void ln_kernel(const float* __restrict__ A,
                          const float* __restrict__ Bsrc,
                          const float* __restrict__ g,
                          const float* __restrict__ bta,
                          float* __restrict__ out,
                          __nv_bfloat16* __restrict__ oh,
                          __nv_bfloat16* __restrict__ ol)
{
    int warp = threadIdx.x >> 5;
    int lane = threadIdx.x & 31;
    int row = blockIdx.x * 8 + warp;
    size_t base = (size_t)row * D;

    const float4* ap = (const float4*)(A + base);
    const float4* bp = (const float4*)(Bsrc + base);
    float4 a0 = ap[lane], a1 = ap[lane + 32];
    float4 b0 = bp[lane], b1 = bp[lane + 32];
    float v[8];
    v[0]=a0.x+b0.x; v[1]=a0.y+b0.y; v[2]=a0.z+b0.z; v[3]=a0.w+b0.w;
    v[4]=a1.x+b1.x; v[5]=a1.y+b1.y; v[6]=a1.z+b1.z; v[7]=a1.w+b1.w;

    float s = 0.f, s2 = 0.f;
    #pragma unroll
    for (int i = 0; i < 8; i++) { s += v[i]; s2 = fmaf(v[i], v[i], s2); }
    #pragma unroll
    for (int o = 16; o > 0; o >>= 1) {
        s  += __shfl_xor_sync(0xffffffffu, s,  o);
        s2 += __shfl_xor_sync(0xffffffffu, s2, o);
    }
    float mu = s * (1.f/256.f);
    float var = s2 * (1.f/256.f) - mu*mu;
    float rstd = rsqrtf(var + 1e-5f);

    const float4* gp = (const float4*)g;
    const float4* tp = (const float4*)bta;
    float4 g0 = gp[lane], g1 = gp[lane+32];
    float4 t0 = tp[lane], t1 = tp[lane+32];
    float4 o0, o1;
    o0.x = (v[0]-mu)*rstd*g0.x + t0.x;
    o0.y = (v[1]-mu)*rstd*g0.y + t0.y;
    o0.z = (v[2]-mu)*rstd*g0.z + t0.z;
    o0.w = (v[3]-mu)*rstd*g0.w + t0.w;
    o1.x = (v[4]-mu)*rstd*g1.x + t1.x;
    o1.y = (v[5]-mu)*rstd*g1.y + t1.y;
    o1.z = (v[6]-mu)*rstd*g1.z + t1.z;
    o1.w = (v[7]-mu)*rstd*g1.w + t1.w;
    float4* op = (float4*)(out + base);
    op[lane]      = o0;
    op[lane + 32] = o1;

    size_t e0 = base + (size_t)lane*4;
    size_t e1 = base + (size_t)(lane+32)*4;
    __nv_bfloat162 lo, hi;
    hi = bsplit2(o0.x, o0.y, &lo);
    *(__nv_bfloat162*)(oh + e0)     = hi; *(__nv_bfloat162*)(ol + e0)     = lo;
    hi = bsplit2(o0.z, o0.w, &lo);
    *(__nv_bfloat162*)(oh + e0 + 2) = hi; *(__nv_bfloat162*)(ol + e0 + 2) = lo;
    hi = bsplit2(o1.x, o1.y, &lo);
    *(__nv_bfloat162*)(oh + e1)     = hi; *(__nv_bfloat162*)(ol + e1)     = lo;
    hi = bsplit2(o1.z, o1.w, &lo);
    *(__nv_bfloat162*)(oh + e1 + 2) = hi; *(__nv_bfloat162*)(ol + e1 + 2) = lo;
}

// ---------------- final: LN cls row only + 2-layer head ----------------------
__global__ void head_kernel(const float* __restrict__ g,
                            const float* __restrict__ bta,
                            const float* __restrict__ Wh1,
                            const float* __restrict__ bh1,
                            const float* __restrict__ Wh2,
                            const float* __restrict__ bh2,
                            float* __restrict__ out)
{
    int b = blockIdx.x;
    int d = threadIdx.x;
    float v = g_x[(size_t)b*SLEN*D + d];

    float s = v, s2 = v*v;
    #pragma unroll
    for (int o = 16; o > 0; o >>= 1) {
        s  += __shfl_xor_sync(0xffffffffu, s,  o);
        s2 += __shfl_xor_sync(0xffffffffu, s2, o);
    }
    __shared__ float ws[8], ws2[8];
    __shared__ float mu_s, rstd_s;
    int w = d >> 5;
    if ((d & 31) == 0) { ws[w] = s; ws2[w] = s2; }
    __syncthreads();
    if (d == 0) {
        float S1 = 0.f, S2 = 0.f;
        #pragma unroll
        for (int i = 0; i < 8; i++) { S1 += ws[i]; S2 += ws2[i]; }
        float mu = S1 * (1.f/256.f);
        float var = S2 * (1.f/256.f) - mu*mu;
        mu_s = mu;
        rstd_s = rsqrtf(var + 1e-5f);
    }
    __syncthreads();

    __shared__ float clsr[256];
    __shared__ float hid[256];
    float c = (v - mu_s) * rstd_s * g[d] + bta[d];
    clsr[d] = c;
    out[b*D + d] = c;                       // cls_out
    __syncthreads();

    float hsum = bh1[d];
    #pragma unroll 8
    for (int k = 0; k < 256; k++) hsum = fmaf(clsr[k], Wh1[k*256 + d], hsum);
    hid[d] = fmaxf(hsum, 0.f);
    __syncthreads();

    if (d < 2) {
        float lg = bh2[d];
        for (int k = 0; k < 256; k++) lg = fmaf(hid[k], Wh2[k*2 + d], lg);
        out[BB*D + b*2 + d] = lg;           // logits after cls_out block
    }
}

// ---------------- launcher ---------------------------------------------------
extern "C" void kernel_launch(void* const* d_in, const int* in_sizes, int n_in,
                              void* d_out, int out_size)
{
    (void)in_sizes; (void)n_in; (void)out_size;

    const float* cf   = (const float*)d_in[0];
    const int*   xc   = (const int*)  d_in[1];
    const int*   yc   = (const int*)  d_in[2];
    const float* Wemb = (const float*)d_in[3];
    const float* bemb = (const float*)d_in[4];
    const float* Wct1 = (const float*)d_in[5];
    const float* bct1 = (const float*)d_in[6];
    const float* Wct2 = (const float*)d_in[7];
    const float* bct2 = (const float*)d_in[8];
    const float* cls  = (const float*)d_in[9];
    const float* Wq = (const float*)d_in[10]; const float* bq = (const float*)d_in[11];
    const float* Wk = (const float*)d_in[12]; const float* bk = (const float*)d_in[13];
    const float* Wv = (const float*)d_in[14]; const float* bv = (const float*)d_in[15];
    const float* Wo = (const float*)d_in[16]; const float* bo = (const float*)d_in[17];
    const float* ln1g = (const float*)d_in[18]; const float* ln1b = (const float*)d_in[19];
    const float* ln2g = (const float*)d_in[20]; const float* ln2b = (const float*)d_in[21];
    const float* Wf1 = (const float*)d_in[22]; const float* bf1 = (const float*)d_in[23];
    const float* Wf2 = (const float*)d_in[24]; const float* bf2 = (const float*)d_in[25];
    const float* lnfg = (const float*)d_in[26]; const float* lnfb = (const float*)d_in[27];
    const float* Wh1 = (const float*)d_in[28]; const float* bh1 = (const float*)d_in[29];
    const float* Wh2 = (const float*)d_in[30]; const float* bh2 = (const float*)d_in[31];
    float* out = (float*)d_out;

    void* p;
    cudaGetSymbolAddress(&p, g_x);  float* xb = (float*)p;
    cudaGetSymbolAddress(&p, g_t);  float* tb = (float*)p;
    cudaGetSymbolAddress(&p, g_xh); __nv_bfloat16* xh = (__nv_bfloat16*)p;
    cudaGetSymbolAddress(&p, g_xl); __nv_bfloat16* xl = (__nv_bfloat16*)p;
    cudaGetSymbolAddress(&p, g_ah); __nv_bfloat16* ah = (__nv_bfloat16*)p;
    cudaGetSymbolAddress(&p, g_al); __nv_bfloat16* al = (__nv_bfloat16*)p;
    cudaGetSymbolAddress(&p, g_hh); __nv_bfloat16* hh = (__nv_bfloat16*)p;
    cudaGetSymbolAddress(&p, g_hl); __nv_bfloat16* hl = (__nv_bfloat16*)p;
    cudaGetSymbolAddress(&p, g_qh); __nv_bfloat16* qh = (__nv_bfloat16*)p;
    cudaGetSymbolAddress(&p, g_ql); __nv_bfloat16* ql = (__nv_bfloat16*)p;
    cudaGetSymbolAddress(&p, g_kh); __nv_bfloat16* kh = (__nv_bfloat16*)p;
    cudaGetSymbolAddress(&p, g_kl); __nv_bfloat16* kl = (__nv_bfloat16*)p;
    cudaGetSymbolAddress(&p, g_vh); __nv_bfloat16* vh = (__nv_bfloat16*)p;
    cudaGetSymbolAddress(&p, g_vl); __nv_bfloat16* vl = (__nv_bfloat16*)p;
    cudaGetSymbolAddress(&p, g_wth); __nv_bfloat16* wth = (__nv_bfloat16*)p;
    cudaGetSymbolAddress(&p, g_wtl); __nv_bfloat16* wtl = (__nv_bfloat16*)p;

    int MB = (MTOK + 63) / 64;             // 129
    dim3 gqkv(MB, D/128, 3);               // 129 x 2 x 3
    dim3 gdd2(MB, D/128);                  // 129 x 2
    dim3 gff (MB, DFF/128);                // 129 x 8
    dim3 gattn((SLEN + 127)/128, NH, BB);  // 9 x 8 x 8
    int lngrid = MTOK / 8;                 // 1025

    // launches 1-5: qkv/wo weight conversion + embed  (6th launch = qkv_mma,
    // so the ncu -s 5 -c 1 capture profiles the dominant GEMM)
    dim3 gdd(D/32, D/32, NL);              // 8 x 8 x 4
    wconv_kernel<<<gdd, 256>>>(Wq, wth + 0,       wtl + 0,       D, D, D*D, 3*D*D);
    wconv_kernel<<<gdd, 256>>>(Wk, wth + D*D,     wtl + D*D,     D, D, D*D, 3*D*D);
    wconv_kernel<<<gdd, 256>>>(Wv, wth + 2*D*D,   wtl + 2*D*D,   D, D, D*D, 3*D*D);
    wconv_kernel<<<gdd, 256>>>(Wo, wth + WOFF_WO, wtl + WOFF_WO, D, D, D*D, D*D);
    embed_kernel<<<MTOK, 256>>>(cf, xc, yc, Wemb, bemb, Wct1, bct1, Wct2, bct2, cls);

    // launch 6: layer-0 QKV (captured by ncu)
    qkv_mma<<<gqkv, 256>>>(xh, xl, wth, wtl, bq, bk, bv,
                           qh, ql, kh, kl, vh, vl);

    // FF weight conversion (needed before f1 of layer 0)
    dim3 gf1(D/32, DFF/32, NL);            // 8 x 32 x 4
    dim3 gf2(DFF/32, D/32, NL);            // 32 x 8 x 4
    wconv_kernel<<<gf1, 256>>>(Wf1, wth + WOFF_F1, wtl + WOFF_F1, D, DFF, D*DFF, D*DFF);
    wconv_kernel<<<gf2, 256>>>(Wf2, wth + WOFF_F2, wtl + WOFF_F2, DFF, D, D*DFF, D*DFF);

    for (int l = 0; l < NL; l++) {
        if (l > 0) {
            qkv_mma<<<gqkv, 256>>>(xh, xl,
                                   wth + (size_t)l*3*D*D, wtl + (size_t)l*3*D*D,
                                   bq + l*D, bk + l*D, bv + l*D,
                                   qh, ql, kh, kl, vh, vl);
        }
        attn_mma_kernel<<<gattn, 256>>>();
        mma_gemm<<<gdd2, 256>>>(ah, al,
                                wth + WOFF_WO + (size_t)l*D*D,
                                wtl + WOFF_WO + (size_t)l*D*D,
                                bo + l*D, tb, nullptr, nullptr, MTOK, D, D, 0);
        ln_kernel<<<lngrid, 256>>>(xb, tb, ln1g + l*D, ln1b + l*D, xb, xh, xl);
        mma_gemm<<<gff, 256>>>(xh, xl,
                               wth + WOFF_F1 + (size_t)l*D*DFF,
                               wtl + WOFF_F1 + (size_t)l*D*DFF,
                               bf1 + l*DFF, nullptr, hh, hl, MTOK, DFF, D, 1);
        mma_gemm<<<gdd2, 256>>>(hh, hl,
                                wth + WOFF_F2 + (size_t)l*D*DFF,
                                wtl + WOFF_F2 + (size_t)l*D*DFF,
                                bf2 + l*D, tb, nullptr, nullptr, MTOK, D, DFF, 0);
        ln_kernel<<<lngrid, 256>>>(xb, tb, ln2g + l*D, ln2b + l*D, xb, xh, xl);
    }

    head_kernel<<<BB, 256>>>(lnfg, lnfb, Wh1, bh1, Wh2, bh2, out);
}